// round 14
// baseline (speedup 1.0000x reference)
#include <cuda_runtime.h>
#include <cuda_bf16.h>
#include <math.h>
#include <stdint.h>

#define D 32
#define HID 64
#define BATCH 2
#define NQ 512
#define NK 512
#define NROWS (BATCH*NQ + BATCH*NK)   // 2048
#define KD 1152                        // logical feature dim
#define KEXT 3456                      // bf16 extended: A=[hi|lo|hi], B=[hi|hi|lo]
#define CHUNK 128                      // bf16 per K-chunk (256 B rows, 2x128B sub-blocks)
#define NCHUNK (KEXT/CHUNK)            // 27
#define STAGES 2
#define HEXT 192                       // hidden ext dim: [hi|lo|hi] / [hi|hi|lo]
#define STAGE_BYTES 24576              // A 16KB + B 8KB per stage (64x32 tile)

// Scratch (device globals: allocation-free rule)
__device__ __nv_bfloat16 g_He [NROWS * HEXT];              // 0.75 MB hidden (A ext)
__device__ __nv_bfloat16 g_W2e[1024 * HEXT];               // 0.38 MB w2^T (B ext)
__device__ float g_L [NROWS * 1024];                       // 8 MB
__device__ __nv_bfloat16 g_Ae[(size_t)BATCH * NQ * KEXT];  // 7 MB
__device__ __nv_bfloat16 g_Be[(size_t)BATCH * NK * KEXT];  // 7 MB

__device__ __forceinline__ uint32_t smem_u32(const void* p) {
    uint32_t a;
    asm("{ .reg .u64 t; cvta.to.shared.u64 t, %1; cvt.u32.u64 %0, t; }"
        : "=r"(a) : "l"(p));
    return a;
}

// ---------------------------------------------------------------------------
// Kernel HW: blocks [0,512): h = silu(x @ w1 + b1) -> g_He rows [hi|lo|hi].
//            blocks [512,768): w2 transpose -> g_W2e[col][hi|hi|lo].
// ---------------------------------------------------------------------------
__global__ void __launch_bounds__(256) kHW(
    const float* __restrict__ Q, const float* __restrict__ K,
    const float* __restrict__ w1, const float* __restrict__ b1,
    const float* __restrict__ w2)
{
    const int tid = threadIdx.x;
    if (blockIdx.x < 512) {
        __shared__ float sx[4 * 32];
        const int rowBase = blockIdx.x * 4;

        if (tid < 128) {
            int r = tid >> 5, c = tid & 31;
            int gr = rowBase + r;
            const float* src = (gr < BATCH * NQ) ? (Q + gr * D)
                                                 : (K + (gr - BATCH * NQ) * D);
            sx[tid] = src[c];
        }
        __syncthreads();

        const int r = tid >> 6;
        const int h = tid & 63;
        float acc = b1[h];
        #pragma unroll
        for (int k = 0; k < 32; k++)
            acc = fmaf(sx[r * 32 + k], w1[k * HID + h], acc);
        float s = 1.f / (1.f + expf(-acc));
        float v = acc * s;

        __nv_bfloat16 hi = __float2bfloat16(v);
        __nv_bfloat16 lo = __float2bfloat16(v - __bfloat162float(hi));
        __nv_bfloat16* E = g_He + (size_t)(rowBase + r) * HEXT;
        E[h] = hi; E[64 + h] = lo; E[128 + h] = hi;
    } else {
        const int idx = (blockIdx.x - 512) * 256 + tid;   // 0..65535
        const int col = idx & 1023;
        const int k   = idx >> 10;
        float v = w2[k * 1024 + col];
        __nv_bfloat16 hi = __float2bfloat16(v);
        __nv_bfloat16 lo = __float2bfloat16(v - __bfloat162float(hi));
        __nv_bfloat16* E = g_W2e + (size_t)col * HEXT;
        E[k] = hi; E[64 + k] = hi; E[128 + k] = lo;
    }
}

// ---------------------------------------------------------------------------
// Kernel Rt: RAW = H @ w2 + b2 on tensor cores (bf16 hi/lo, K_ext=192),
// fused L transform -> g_L (fp32). 64x64 tile, 128 thr.
// ---------------------------------------------------------------------------
__global__ void __launch_bounds__(128) kRt(const float* __restrict__ b2)
{
    __shared__ __align__(1024) uint8_t sbuf[3 * 16384];   // 48 KB

    const int tid  = threadIdx.x;
    const int wid  = tid >> 5;
    const int lane = tid & 31;
    const int wm = wid & 1;
    const int wn = wid >> 1;
    const int rowBase = blockIdx.y * 64;
    const int colBase = blockIdx.x * 64;

    const uint32_t sb = smem_u32(sbuf);

    #pragma unroll
    for (int c = 0; c < 3; c++) {
        uint32_t base = sb + c * 16384;
        #pragma unroll
        for (int p = 0; p < 8; p++) {
            int idx = tid + p * 128;
            int isB = idx >> 9;
            int li  = idx & 511;
            int row = li >> 3;
            int q   = li & 7;
            const __nv_bfloat16* src = isB
                ? (g_W2e + (size_t)(colBase + row) * HEXT + c * 64 + q * 8)
                : (g_He  + (size_t)(rowBase + row) * HEXT + c * 64 + q * 8);
            uint32_t d = base + (uint32_t)(isB * 8192 + row * 128 + ((q ^ (row & 7)) << 4));
            asm volatile("cp.async.cg.shared.global [%0], [%1], 16;"
                         :: "r"(d), "l"((const void*)src) : "memory");
        }
    }
    asm volatile("cp.async.commit_group;" ::: "memory");
    asm volatile("cp.async.wait_group 0;" ::: "memory");
    __syncthreads();

    float acc[2][4][4] = {};
    const int tile = lane >> 3;
    const int rin  = lane & 7;
    const int rofs = ((tile & 1) << 3) + rin;

    #pragma unroll
    for (int c = 0; c < 3; c++) {
        const uint32_t Ab = sb + c * 16384;
        const uint32_t Bb = Ab + 8192;
        #pragma unroll
        for (int ks = 0; ks < 4; ks++) {
            const int ku = 2 * ks + (tile >> 1);
            uint32_t a[2][4], bb[2][4];
            #pragma unroll
            for (int mt = 0; mt < 2; mt++) {
                int r = wm * 32 + mt * 16 + rofs;
                uint32_t ad = Ab + r * 128 + ((ku ^ (r & 7)) << 4);
                asm volatile(
                    "ldmatrix.sync.aligned.m8n8.x4.shared.b16 {%0,%1,%2,%3}, [%4];"
                    : "=r"(a[mt][0]), "=r"(a[mt][1]), "=r"(a[mt][2]), "=r"(a[mt][3])
                    : "r"(ad));
            }
            #pragma unroll
            for (int nt = 0; nt < 2; nt++) {
                int r = wn * 32 + nt * 16 + rofs;
                uint32_t bd = Bb + r * 128 + ((ku ^ (r & 7)) << 4);
                asm volatile(
                    "ldmatrix.sync.aligned.m8n8.x4.shared.b16 {%0,%1,%2,%3}, [%4];"
                    : "=r"(bb[nt][0]), "=r"(bb[nt][1]), "=r"(bb[nt][2]), "=r"(bb[nt][3])
                    : "r"(bd));
            }
            #pragma unroll
            for (int mt = 0; mt < 2; mt++) {
                #pragma unroll
                for (int j = 0; j < 4; j++) {
                    uint32_t b0 = bb[j >> 1][(j & 1)];
                    uint32_t b1 = bb[j >> 1][(j & 1) + 2];
                    asm volatile(
                        "mma.sync.aligned.m16n8k16.row.col.f32.bf16.bf16.f32 "
                        "{%0,%1,%2,%3}, {%4,%5,%6,%7}, {%8,%9}, {%0,%1,%2,%3};"
                        : "+f"(acc[mt][j][0]), "+f"(acc[mt][j][1]),
                          "+f"(acc[mt][j][2]), "+f"(acc[mt][j][3])
                        : "r"(a[mt][0]), "r"(a[mt][1]), "r"(a[mt][2]), "r"(a[mt][3]),
                          "r"(b0), "r"(b1));
                }
            }
        }
    }

    const int g = lane >> 2;
    const int t2 = (lane & 3) * 2;
    #pragma unroll
    for (int mt = 0; mt < 2; mt++) {
        #pragma unroll
        for (int j = 0; j < 4; j++) {
            int e = colBase + wn * 32 + j * 8 + t2;
            float2 bv = *reinterpret_cast<const float2*>(&b2[e]);
            #pragma unroll
            for (int half = 0; half < 2; half++) {
                int gr = rowBase + wm * 32 + mt * 16 + g + half * 8;
                float rw0 = acc[mt][j][half * 2 + 0] + bv.x;
                float rw1 = acc[mt][j][half * 2 + 1] + bv.y;
                float2 o;
                #pragma unroll
                for (int q = 0; q < 2; q++) {
                    int ee = e + q;
                    int ii = ee >> 5, jj = ee & 31;
                    float raw = q ? rw1 : rw0;
                    float t = 5.f * tanhf(raw * 0.2f);
                    float Lv;
                    if (jj > ii) {
                        Lv = 0.f;
                    } else if (jj == ii) {
                        float z = t + 1.f;
                        Lv = fmaxf(z, 0.f) + log1pf(expf(-fabsf(z))) + 1e-4f;
                    } else {
                        Lv = t;
                    }
                    if (q) o.y = Lv; else o.x = Lv;
                }
                *reinterpret_cast<float2*>(&g_L[(size_t)gr * 1024 + e]) = o;
            }
        }
    }
}

// ---------------------------------------------------------------------------
// Kernel B2: per-row G = L L^T, u = G x, a = x^T G x; bf16 hi/lo stores.
// Padded smem (stride 33), register-tiled 2x2 G; 4-wide vectorized stores.
// ---------------------------------------------------------------------------
__device__ __forceinline__ void store3(__nv_bfloat16* __restrict__ E, int e,
                                       float v, bool isA)
{
    __nv_bfloat16 h = __float2bfloat16(v);
    __nv_bfloat16 l = __float2bfloat16(v - __bfloat162float(h));
    E[e] = h;
    E[1152 + e] = isA ? l : h;
    E[2304 + e] = isA ? h : l;
}

__global__ void __launch_bounds__(256) kB2(
    const float* __restrict__ Q, const float* __restrict__ K)
{
    __shared__ float sL[32 * 33];
    __shared__ float sG[32 * 33];
    __shared__ float sx[32];

    const int tid = threadIdx.x;
    const int gr = blockIdx.x;
    const bool isA = (gr < BATCH * NQ);
    const float* src = isA ? (Q + gr * D) : (K + (gr - BATCH * NQ) * D);

    {   // float4 global load -> padded scalar stores (conflict-free)
        float4 v = *reinterpret_cast<const float4*>(&g_L[(size_t)gr * 1024 + tid * 4]);
        int row = tid >> 3, col = (tid & 7) * 4;
        float* d = &sL[row * 33 + col];
        d[0] = v.x; d[1] = v.y; d[2] = v.z; d[3] = v.w;
    }
    if (tid < 32) sx[tid] = src[tid];
    __syncthreads();

    // G = L L^T via 2x2 register tile per thread (full-32 dot; upper zeros
    // make it exact). i0 = 2*(tid>>4), j0 = 2*(tid&15).
    {
        const int i0 = (tid >> 4) << 1;
        const int j0 = (tid & 15) << 1;
        float g00 = 0.f, g01 = 0.f, g10 = 0.f, g11 = 0.f;
        const float* Ra = &sL[i0 * 33];
        const float* Rb = &sL[j0 * 33];
        #pragma unroll
        for (int tt = 0; tt < 32; tt++) {
            float a0 = Ra[tt], a1 = Ra[33 + tt];
            float b0 = Rb[tt], b1 = Rb[33 + tt];
            g00 = fmaf(a0, b0, g00);
            g01 = fmaf(a0, b1, g01);
            g10 = fmaf(a1, b0, g10);
            g11 = fmaf(a1, b1, g11);
        }
        sG[i0 * 33 + j0]            = g00;
        sG[i0 * 33 + j0 + 1]        = g01;
        sG[(i0 + 1) * 33 + j0]      = g10;
        sG[(i0 + 1) * 33 + j0 + 1]  = g11;
    }
    __syncthreads();

    __nv_bfloat16* E = isA ? (g_Ae + (size_t)gr * KEXT)
                           : (g_Be + (size_t)(gr - BATCH * NQ) * KEXT);

    if (tid < 32) {
        float u = 0.f;
        #pragma unroll
        for (int j = 0; j < 32; j++)
            u = fmaf(sG[tid * 33 + j], sx[j], u);
        float prod = u * sx[tid];
        #pragma unroll
        for (int off = 16; off > 0; off >>= 1)
            prod += __shfl_xor_sync(0xffffffffu, prod, off);
        store3(E, 1056 + tid, isA ? u : -2.f * sx[tid], isA);
        store3(E, 1088 + tid, isA ? sx[tid] : -2.f * u, isA);
        if (tid == 0) {
            store3(E, 1120, isA ? prod : 1.f, isA);
            store3(E, 1121, isA ? 1.f : prod, isA);
        }
    }
    if (tid < 30) store3(E, 1122 + tid, 0.f, isA);

    // packed quadratic features: 4 consecutive e per thread -> 8B stores
    if (tid < 132) {
        int e = tid * 4;
        int i = (int)((sqrtf(8.f * (float)e + 1.f) - 1.f) * 0.5f);
        while ((i + 1) * (i + 2) / 2 <= e) i++;
        while (i * (i + 1) / 2 > e) i--;
        int j = e - ((i * (i + 1)) >> 1);

        union U2 { __nv_bfloat16 b[4]; uint2 u; };
        U2 Gh, Gl, Xh, Xl;
        #pragma unroll
        for (int q = 0; q < 4; q++) {
            float g = sG[i * 33 + j];
            float packG = (i == j) ? g : 2.f * g;
            float xx = sx[i] * sx[j];
            __nv_bfloat16 gh = __float2bfloat16(packG);
            Gh.b[q] = gh;
            Gl.b[q] = __float2bfloat16(packG - __bfloat162float(gh));
            __nv_bfloat16 xh = __float2bfloat16(xx);
            Xh.b[q] = xh;
            Xl.b[q] = __float2bfloat16(xx - __bfloat162float(xh));
            if (++j > i) { i++; j = 0; }
        }
        uint2 s0h = isA ? Gh.u : Xh.u;
        uint2 s0l = isA ? Gl.u : Xl.u;
        uint2 s1h = isA ? Xh.u : Gh.u;
        uint2 s1l = isA ? Xl.u : Gl.u;
        *reinterpret_cast<uint2*>(E + e)              = s0h;
        *reinterpret_cast<uint2*>(E + 528 + e)        = s1h;
        *reinterpret_cast<uint2*>(E + 1152 + e)       = isA ? s0l : s0h;
        *reinterpret_cast<uint2*>(E + 1152 + 528 + e) = isA ? s1l : s1h;
        *reinterpret_cast<uint2*>(E + 2304 + e)       = isA ? s0h : s0l;
        *reinterpret_cast<uint2*>(E + 2304 + 528 + e) = isA ? s1h : s1l;
    }
}

// ---------------------------------------------------------------------------
// Kernel Cm: bf16 mma.sync GEMM.  out[b,n,m] = sqrt(clip(0.5 * Ae[n].Be[m]))
// CTA tile 64(M)x32(N), 128 thr = 2x2 warps, warp tile 32x16, grid 256 CTAs.
// CHUNK=128 (two 128B sub-blocks per row), 2-stage pipeline, ONE barrier +
// ONE wait per chunk (27 total):
//   wait(0) -> bar -> issue c+1 (buffer freed by compute c-1) -> compute c
// xor swizzle within each sub-block, fragment double-buffering across 8 ks.
// ---------------------------------------------------------------------------
__global__ void __launch_bounds__(128) kCm(float* __restrict__ out)
{
    __shared__ __align__(1024) uint8_t sbuf[STAGES * STAGE_BYTES];   // 48 KB

    const int tid  = threadIdx.x;
    const int wid  = tid >> 5;
    const int lane = tid & 31;
    const int wm = wid & 1;          // M warp coord (2) -> 32 rows
    const int wn = wid >> 1;         // N warp coord (2) -> 16 cols
    const int b  = blockIdx.z;
    const int aRow0 = b * NQ + blockIdx.y * 64;
    const int bRow0 = b * NK + blockIdx.x * 32;

    const uint32_t sb = smem_u32(sbuf);

    // per-thread cp.async src/dst: 12 x 16B per chunk
    // A: 64 rows x 16 units (two 8KB sub-blocks); B: 32 rows x 16 units (two 4KB)
    const __nv_bfloat16* srcP[12];
    uint32_t dstOff[12];
    #pragma unroll
    for (int p = 0; p < 12; p++) {
        int idx = tid + p * 128;          // 0..1535
        if (idx < 1024) {                 // A
            int row = idx >> 4, q = idx & 15;
            srcP[p] = g_Ae + (size_t)(aRow0 + row) * KEXT + q * 8;
            dstOff[p] = (uint32_t)((q >> 3) * 8192 + row * 128 +
                                   (((q & 7) ^ (row & 7)) << 4));
        } else {                          // B
            int li = idx - 1024;
            int row = li >> 4, q = li & 15;
            srcP[p] = g_Be + (size_t)(bRow0 + row) * KEXT + q * 8;
            dstOff[p] = (uint32_t)(16384 + (q >> 3) * 4096 + row * 128 +
                                   (((q & 7) ^ (row & 7)) << 4));
        }
    }

    #define ISSUE(c, s)                                                        \
        do {                                                                   \
            uint32_t base_ = sb + (s) * STAGE_BYTES;                           \
            _Pragma("unroll")                                                  \
            for (int p_ = 0; p_ < 12; p_++) {                                  \
                uint32_t d_ = base_ + dstOff[p_];                              \
                const void* g_ = (const void*)(srcP[p_] + (c) * CHUNK);        \
                asm volatile("cp.async.cg.shared.global [%0], [%1], 16;"       \
                             :: "r"(d_), "l"(g_) : "memory");                  \
            }                                                                  \
        } while (0)

    ISSUE(0, 0); asm volatile("cp.async.commit_group;" ::: "memory");

    float acc[2][2][4] = {};   // [mt][j][c0..c3]
    const int tile = lane >> 3;
    const int rin  = lane & 7;
    const int rofs = ((tile & 1) << 3) + rin;
    const int arow0 = wm * 32 + rofs;          // +16 per mt
    const int brow  = wn * 16 + rofs;          // single n16 tile per warp

    uint32_t fa[2][2][4], fb[2][4];   // [buf][mt][reg] / [buf][reg]

    // ks in 0..7; ku = 2*ks + (tile>>1) in 0..15 -> sub-block ku>>3, kw = ku&7
    #define LOADFRAG(ks, buf, Ab, Bb)                                          \
        do {                                                                   \
            const int ku_ = 2 * (ks) + (tile >> 1);                            \
            const int sub_ = ku_ >> 3;                                         \
            const int kw_ = ku_ & 7;                                           \
            _Pragma("unroll")                                                  \
            for (int mt_ = 0; mt_ < 2; mt_++) {                                \
                int r_ = arow0 + mt_ * 16;                                     \
                uint32_t ad_ = (Ab) + sub_ * 8192 + r_ * 128 +                 \
                               ((kw_ ^ (r_ & 7)) << 4);                        \
                asm volatile(                                                  \
                    "ldmatrix.sync.aligned.m8n8.x4.shared.b16 {%0,%1,%2,%3}, [%4];" \
                    : "=r"(fa[buf][mt_][0]), "=r"(fa[buf][mt_][1]),            \
                      "=r"(fa[buf][mt_][2]), "=r"(fa[buf][mt_][3])             \
                    : "r"(ad_));                                               \
            }                                                                  \
            {                                                                  \
                int r_ = brow;                                                 \
                uint32_t bd_ = (Bb) + sub_ * 4096 + r_ * 128 +                 \
                               ((kw_ ^ (r_ & 7)) << 4);                        \
                asm volatile(                                                  \
                    "ldmatrix.sync.aligned.m8n8.x4.shared.b16 {%0,%1,%2,%3}, [%4];" \
                    : "=r"(fb[buf][0]), "=r"(fb[buf][1]),                      \
                      "=r"(fb[buf][2]), "=r"(fb[buf][3])                       \
                    : "r"(bd_));                                               \
            }                                                                  \
        } while (0)

    for (int c = 0; c < NCHUNK; c++) {
        asm volatile("cp.async.wait_group 0;" ::: "memory");
        __syncthreads();

        // issue chunk c+1 into the buffer freed by compute c-1 (barrier-ordered);
        // its load overlaps compute of chunk c below
        if (c + 1 < NCHUNK) ISSUE(c + 1, (c + 1) & 1);
        asm volatile("cp.async.commit_group;" ::: "memory");

        const uint32_t Ab = sb + (c & 1) * STAGE_BYTES;
        const uint32_t Bb = Ab + 16384;

        LOADFRAG(0, 0, Ab, Bb);
        #pragma unroll
        for (int ks = 0; ks < 8; ks++) {
            const int cur = ks & 1;
            if (ks < 7) LOADFRAG(ks + 1, cur ^ 1, Ab, Bb);
            #pragma unroll
            for (int mt = 0; mt < 2; mt++) {
                #pragma unroll
                for (int j = 0; j < 2; j++) {
                    uint32_t b0 = fb[cur][j];
                    uint32_t b1 = fb[cur][j + 2];
                    asm volatile(
                        "mma.sync.aligned.m16n8k16.row.col.f32.bf16.bf16.f32 "
                        "{%0,%1,%2,%3}, {%4,%5,%6,%7}, {%8,%9}, {%0,%1,%2,%3};"
                        : "+f"(acc[mt][j][0]), "+f"(acc[mt][j][1]),
                          "+f"(acc[mt][j][2]), "+f"(acc[mt][j][3])
                        : "r"(fa[cur][mt][0]), "r"(fa[cur][mt][1]),
                          "r"(fa[cur][mt][2]), "r"(fa[cur][mt][3]),
                          "r"(b0), "r"(b1));
                }
            }
        }
    }

    const int g = lane >> 2;
    const int t2 = (lane & 3) * 2;
    #pragma unroll
    for (int mt = 0; mt < 2; mt++) {
        int n = blockIdx.y * 64 + wm * 32 + mt * 16 + g;
        #pragma unroll
        for (int j = 0; j < 2; j++) {
            int m = blockIdx.x * 32 + wn * 16 + j * 8 + t2;
            float d0 = 0.5f * acc[mt][j][0];
            float d1 = 0.5f * acc[mt][j][1];
            float d2 = 0.5f * acc[mt][j][2];
            float d3 = 0.5f * acc[mt][j][3];
            d0 = fminf(fmaxf(d0, 1e-6f), 1e6f);
            d1 = fminf(fmaxf(d1, 1e-6f), 1e6f);
            d2 = fminf(fmaxf(d2, 1e-6f), 1e6f);
            d3 = fminf(fmaxf(d3, 1e-6f), 1e6f);
            float2 lo = make_float2(sqrtf(d0), sqrtf(d1));
            float2 hi = make_float2(sqrtf(d2), sqrtf(d3));
            *reinterpret_cast<float2*>(&out[((size_t)(b * NQ + n) * NK) + m]) = lo;
            *reinterpret_cast<float2*>(&out[((size_t)(b * NQ + n + 8) * NK) + m]) = hi;
        }
    }
    #undef ISSUE
    #undef LOADFRAG
}

// ---------------------------------------------------------------------------
extern "C" void kernel_launch(void* const* d_in, const int* in_sizes, int n_in,
                              void* d_out, int out_size)
{
    const float* Q  = (const float*)d_in[0];
    const float* K  = (const float*)d_in[1];
    const float* w1 = (const float*)d_in[2];
    const float* b1 = (const float*)d_in[3];
    const float* w2 = (const float*)d_in[4];
    const float* b2 = (const float*)d_in[5];
    float* out = (float*)d_out;

    kHW<<<768, 256>>>(Q, K, w1, b1, w2);
    dim3 grt(1024 / 64, NROWS / 64);
    kRt<<<grt, 128>>>(b2);
    kB2<<<NROWS, 256>>>(Q, K);
    dim3 gc(NK / 32, NQ / 64, BATCH);
    kCm<<<gc, 128>>>(out);
}